// round 4
// baseline (speedup 1.0000x reference)
#include <cuda_runtime.h>
#include <cuda_fp16.h>
#include <math.h>
#include <stdint.h>

#define BB   32
#define SS   512
#define DD   768
#define HH   384
#define G3   (3*HH)      // 1152
#define NROWS (2*G3)     // 2304
#define M16K (SS*BB)     // 16384
#define KC   (3*DD)      // 2304  (split-concat K)

// ---------------- scratch (static device globals; no runtime alloc) ----------
__device__ float g_XW[(size_t)NROWS * M16K];        // [n][m], m = t*32+b
__device__ float g_OUT[(size_t)M16K * (2*HH)];      // [m][768]
__device__ float g_H[2][2][HH * BB];                // [dir][buf][k*32+b]
__device__ int   g_bar[2 * SS];
__device__ float g_scores[M16K];
// fp16 split-concat operands
__device__ __half g_Ac [(size_t)NROWS * KC];        // proj A: [Wh|Wh|Wl]
__device__ __half g_Bc [(size_t)M16K  * KC];        // proj B: [Xh|Xl|Xh]
__device__ __half g_Wac[(size_t)(2*HH) * KC];       // attn A: [Wah|Wah|Wal]
__device__ __half g_Oc [(size_t)M16K  * KC];        // attn B: [Oh|Ol|Oh]

// ============================ PTX helpers (sm_80/sm_100-base safe) ===========
__device__ __forceinline__ uint32_t smem_u32(const void* p) {
    uint32_t a;
    asm("{ .reg .u64 t; cvta.to.shared.u64 t, %1; cvt.u32.u64 %0, t; }"
        : "=r"(a) : "l"(p));
    return a;
}

#define CP_ASYNC16(saddr, gptr) \
    asm volatile("cp.async.cg.shared.global [%0], [%1], 16;" \
                 :: "r"(saddr), "l"(gptr) : "memory")
#define CP_COMMIT() asm volatile("cp.async.commit_group;" ::: "memory")
#define CP_WAIT2()  asm volatile("cp.async.wait_group 2;" ::: "memory")

#define LDMATRIX_X4(r0, r1, r2, r3, addr) \
    asm volatile("ldmatrix.sync.aligned.m8n8.x4.shared.b16 {%0,%1,%2,%3}, [%4];" \
                 : "=r"(r0), "=r"(r1), "=r"(r2), "=r"(r3) : "r"(addr))

#define MMA16816(c0, c1, c2, c3, a0, a1, a2, a3, b0, b1) \
    asm volatile("mma.sync.aligned.m16n8k16.row.col.f32.f16.f16.f32 " \
                 "{%0,%1,%2,%3}, {%4,%5,%6,%7}, {%8,%9}, {%0,%1,%2,%3};" \
                 : "+f"(c0), "+f"(c1), "+f"(c2), "+f"(c3) \
                 : "r"(a0), "r"(a1), "r"(a2), "r"(a3), "r"(b0), "r"(b1))

// packed fp32x2 (Blackwell base-family)
__device__ __forceinline__ unsigned long long pk2(float a, float b) {
    unsigned long long r;
    asm("mov.b64 %0, {%1, %2};" : "=l"(r) : "f"(a), "f"(b));
    return r;
}
__device__ __forceinline__ float2 upk2(unsigned long long v) {
    float2 f;
    asm("mov.b64 {%0, %1}, %2;" : "=f"(f.x), "=f"(f.y) : "l"(v));
    return f;
}
#define FMA2(d, a, b, c) \
    asm("fma.rn.f32x2 %0, %1, %2, %3;" : "=l"(d) : "l"(a), "l"(b), "l"(c))

// ---------------------------------- init ------------------------------------
__global__ void init_kernel() {
    int idx = blockIdx.x * blockDim.x + threadIdx.x;
    int nthr = gridDim.x * blockDim.x;
    float* h = &g_H[0][0][0];
    for (int i = idx; i < 2 * 2 * HH * BB; i += nthr) h[i] = 0.f;
    for (int i = idx; i < 2 * SS; i += nthr) g_bar[i] = 0;
    for (int i = idx; i < M16K; i += nthr) g_scores[i] = 0.f;
}

// ---------------- fp32 -> fp16 hi/lo split + K-concat conversion -------------
// rows [0, M16K)              : X  -> g_Bc   segs [h | l | h]
// rows [M16K, M16K+NROWS)     : Wcat -> g_Ac segs [h | h | l]
// rows [M16K+NROWS, +768)     : Wa -> g_Wac  segs [h | h | l]
__global__ void __launch_bounds__(256) convert_split(
    const float* __restrict__ ip,
    const float* __restrict__ Wf, const float* __restrict__ Wb,
    const float* __restrict__ Wa)
{
    const int TOT = (M16K + NROWS + 2 * HH) * (DD / 4);
    int idx = blockIdx.x * blockDim.x + threadIdx.x;
    if (idx >= TOT) return;
    int row = idx / (DD / 4);
    int k = (idx - row * (DD / 4)) * 4;

    const float* src;
    __half* dst;
    bool isA;
    if (row < M16K) {
        int b = row & 31, t = row >> 5;
        src = ip + ((size_t)(b * SS + t)) * DD + k;
        dst = g_Bc + (size_t)row * KC;
        isA = false;
    } else if (row < M16K + NROWS) {
        int n = row - M16K;
        src = ((n < G3) ? (Wf + (size_t)n * DD) : (Wb + (size_t)(n - G3) * DD)) + k;
        dst = g_Ac + (size_t)n * KC;
        isA = true;
    } else {
        int n = row - M16K - NROWS;
        src = Wa + (size_t)n * (2 * HH) + k;
        dst = g_Wac + (size_t)n * KC;
        isA = true;
    }
    float4 v = *(const float4*)src;
    union { __half h[4]; uint2 u; } hi, lo;
    hi.h[0] = __float2half_rn(v.x); lo.h[0] = __float2half_rn(v.x - __half2float(hi.h[0]));
    hi.h[1] = __float2half_rn(v.y); lo.h[1] = __float2half_rn(v.y - __half2float(hi.h[1]));
    hi.h[2] = __float2half_rn(v.z); lo.h[2] = __float2half_rn(v.z - __half2float(hi.h[2]));
    hi.h[3] = __float2half_rn(v.w); lo.h[3] = __float2half_rn(v.w - __half2float(hi.h[3]));

    if (isA) {   // [h | h | l]
        *(uint2*)(dst + k)          = hi.u;
        *(uint2*)(dst + DD + k)     = hi.u;
        *(uint2*)(dst + 2 * DD + k) = lo.u;
    } else {     // [h | l | h]
        *(uint2*)(dst + k)          = hi.u;
        *(uint2*)(dst + DD + k)     = lo.u;
        *(uint2*)(dst + 2 * DD + k) = hi.u;
    }
}

// -------------------- OUT fp32 -> fp16 split-concat (for attn HGEMM) --------
__global__ void __launch_bounds__(256) out_convert() {
    int idx = blockIdx.x * blockDim.x + threadIdx.x;   // over M16K * 192
    if (idx >= M16K * (DD / 4)) return;
    int m = idx / (DD / 4);
    int k = (idx - m * (DD / 4)) * 4;
    float4 v = *(const float4*)&g_OUT[(size_t)m * (2 * HH) + k];
    union { __half h[4]; uint2 u; } hi, lo;
    hi.h[0] = __float2half_rn(v.x); lo.h[0] = __float2half_rn(v.x - __half2float(hi.h[0]));
    hi.h[1] = __float2half_rn(v.y); lo.h[1] = __float2half_rn(v.y - __half2float(hi.h[1]));
    hi.h[2] = __float2half_rn(v.z); lo.h[2] = __float2half_rn(v.z - __half2float(hi.h[2]));
    hi.h[3] = __float2half_rn(v.w); lo.h[3] = __float2half_rn(v.w - __half2float(hi.h[3]));
    __half* dst = g_Oc + (size_t)m * KC;
    *(uint2*)(dst + k)          = hi.u;   // [h | l | h]
    *(uint2*)(dst + DD + k)     = lo.u;
    *(uint2*)(dst + 2 * DD + k) = hi.u;
}

// ----------------------- shared HGEMM (mma.sync) -----------------------------
// C[n 128][m 128] = A[n][K=2304] * B[m][K]^T. 8 warps = 2(n) x 4(m).
// MODE 0: proj epilogue (bias add, store g_XW).  MODE 1: attn epilogue.
#define HG_STAGE_BYTES 10240            // 128 rows * 80B
#define HG_DYN_SMEM    (8 * HG_STAGE_BYTES)

template <int MODE>
__global__ void __launch_bounds__(256, 2) hgemm_kernel(
    const __half* __restrict__ Ag, const __half* __restrict__ Bg,
    const float* __restrict__ e0, const float* __restrict__ e1)
{
    extern __shared__ char dyn[];
    const uint32_t Abase = smem_u32(dyn);
    const uint32_t Bbase = Abase + 4 * HG_STAGE_BYTES;

    const int tid  = threadIdx.x;
    const int wid  = tid >> 5, lane = tid & 31;
    const int wn   = wid >> 2;
    const int wm   = wid & 3;
    const int n0   = blockIdx.x * 128;
    const int m0   = blockIdx.y * 128;

    const int KT = KC / 32;               // 72

    auto load_stage = [&](int buf, int kt) {
        uint32_t as = Abase + buf * HG_STAGE_BYTES;
        uint32_t bs = Bbase + buf * HG_STAGE_BYTES;
#pragma unroll
        for (int i = 0; i < 2; ++i) {
            int idx = tid + i * 256;
            int row = idx >> 2, c = idx & 3;
            const __half* ga = Ag + (size_t)(n0 + row) * KC + kt * 32 + c * 8;
            CP_ASYNC16(as + row * 80 + c * 16, ga);
            const __half* gb = Bg + (size_t)(m0 + row) * KC + kt * 32 + c * 8;
            CP_ASYNC16(bs + row * 80 + c * 16, gb);
        }
        CP_COMMIT();
    };

    float acc[4][4][4];
#pragma unroll
    for (int i = 0; i < 4; i++)
#pragma unroll
        for (int j = 0; j < 4; j++)
#pragma unroll
            for (int r = 0; r < 4; r++) acc[i][j][r] = 0.f;

    load_stage(0, 0);
    load_stage(1, 1);
    load_stage(2, 2);

    const int lr = lane & 15;
    const int lc = lane >> 4;

    for (int kt = 0; kt < KT; ++kt) {
        CP_WAIT2();
        __syncthreads();
        if (kt + 3 < KT) load_stage((kt + 3) & 3, kt + 3);
        else CP_COMMIT();

        uint32_t as = Abase + (kt & 3) * HG_STAGE_BYTES;
        uint32_t bs = Bbase + (kt & 3) * HG_STAGE_BYTES;

#pragma unroll
        for (int kk = 0; kk < 2; ++kk) {
            uint32_t bfr[4][2];
#pragma unroll
            for (int bm = 0; bm < 2; ++bm) {
                uint32_t r0, r1, r2, r3;
                uint32_t addr = bs + (wm * 32 + bm * 16 + lr) * 80 + (kk * 2 + lc) * 16;
                LDMATRIX_X4(r0, r1, r2, r3, addr);
                bfr[bm * 2 + 0][0] = r0; bfr[bm * 2 + 0][1] = r2;
                bfr[bm * 2 + 1][0] = r1; bfr[bm * 2 + 1][1] = r3;
            }
#pragma unroll
            for (int fn = 0; fn < 4; ++fn) {
                uint32_t a0, a1, a2, a3;
                uint32_t addr = as + (wn * 64 + fn * 16 + lr) * 80 + (kk * 2 + lc) * 16;
                LDMATRIX_X4(a0, a1, a2, a3, addr);
#pragma unroll
                for (int fm = 0; fm < 4; ++fm) {
                    MMA16816(acc[fn][fm][0], acc[fn][fm][1], acc[fn][fm][2], acc[fn][fm][3],
                             a0, a1, a2, a3, bfr[fm][0], bfr[fm][1]);
                }
            }
        }
        __syncthreads();
    }

    if (MODE == 0) {
        // ---- proj epilogue: bias + coalesced g_XW store via smem ----
        float* Cs = (float*)dyn;             // [128][136]
        const int crow = lane >> 2;
        const int ccol = 2 * (lane & 3);
#pragma unroll
        for (int fn = 0; fn < 4; ++fn) {
#pragma unroll
            for (int fm = 0; fm < 4; ++fm) {
                int r = wn * 64 + fn * 16 + crow;
                int c = wm * 32 + fm * 8 + ccol;
                Cs[r * 136 + c]           = acc[fn][fm][0];
                Cs[r * 136 + c + 1]       = acc[fn][fm][1];
                Cs[(r + 8) * 136 + c]     = acc[fn][fm][2];
                Cs[(r + 8) * 136 + c + 1] = acc[fn][fm][3];
            }
        }
        __syncthreads();
#pragma unroll
        for (int it = 0; it < 16; ++it) {
            int idx = tid + it * 256;
            int row = idx >> 5, cq = idx & 31;
            int n = n0 + row;
            float bv = (n < G3) ? __ldg(e0 + n) : __ldg(e1 + n - G3);
            float4 v;
            v.x = Cs[row * 136 + cq * 4 + 0] + bv;
            v.y = Cs[row * 136 + cq * 4 + 1] + bv;
            v.z = Cs[row * 136 + cq * 4 + 2] + bv;
            v.w = Cs[row * 136 + cq * 4 + 3] + bv;
            *(float4*)&g_XW[(size_t)n * M16K + m0 + cq * 4] = v;
        }
    } else {
        // ---- attn epilogue: tanh(acc + ba[n]) * ctx[n], reduce over n ----
        float* Msum = (float*)dyn;           // [128]
        if (tid < 128) Msum[tid] = 0.f;
        __syncthreads();
        const int crow = lane >> 2;
        const int ccol = 2 * (lane & 3);
#pragma unroll
        for (int fm = 0; fm < 4; ++fm) {
            int c = wm * 32 + fm * 8 + ccol;
            float s0 = 0.f, s1 = 0.f;
#pragma unroll
            for (int fn = 0; fn < 4; ++fn) {
                int na = n0 + wn * 64 + fn * 16 + crow;
                int nb = na + 8;
                float ba_a = __ldg(e0 + na), ba_b = __ldg(e0 + nb);
                float cx_a = __ldg(e1 + na), cx_b = __ldg(e1 + nb);
                s0 += tanhf(acc[fn][fm][0] + ba_a) * cx_a
                    + tanhf(acc[fn][fm][2] + ba_b) * cx_b;
                s1 += tanhf(acc[fn][fm][1] + ba_a) * cx_a
                    + tanhf(acc[fn][fm][3] + ba_b) * cx_b;
            }
            atomicAdd(&Msum[c], s0);
            atomicAdd(&Msum[c + 1], s1);
        }
        __syncthreads();
        if (tid < 128) atomicAdd(&g_scores[m0 + tid], Msum[tid]);
    }
}

// ---------------------------- GRU recurrence (f32x2) -------------------------
// 128 CTAs: 64/dir, 6 units each. 96 threads: 3 warps x (2 units x 16 batch-pairs).
// smem floats: Ws2 18x792=14256 | Hs 12288 | xs 576 | bh 32 | Hn 192
#define REC_THREADS 96
#define WS2_STRIDE  792
#define REC_SMEM_FLOATS (18*WS2_STRIDE + 12288 + 576 + 32 + 192)

__global__ void __launch_bounds__(REC_THREADS) gru_rec(
    const float* __restrict__ Whf, const float* __restrict__ Whb,
    const float* __restrict__ bhf, const float* __restrict__ bhb)
{
    extern __shared__ float sm[];
    float* Ws2 = sm;                           // 14256
    float* Hs  = sm + 18 * WS2_STRIDE;         // 12288
    float* xs  = Hs + 12288;                   // 576
    float* bh  = xs + 576;                     // 32
    float* Hn  = bh + 32;                      // 192

    const int bid = blockIdx.x;
    const int dir = bid >> 6;
    const int u0  = (bid & 63) * 6;
    const int tid = threadIdx.x;
    const int w = tid >> 5, lane = tid & 31;
    const int uu = lane >> 4;                  // 0..1 (half-warp unit)
    const int p  = lane & 15;                  // batch pair
    const int ul = 2 * w + uu;                 // local unit 0..5
    const int j  = u0 + ul;                    // global unit

    const float* Wh  = dir ? Whb : Whf;
    const float* bhh = dir ? bhb : bhf;

    // pair-duplicated stationary weights: Ws2[ru*792 + 2k {,+1}] = W_hh[g*384+u0+u][k]
    for (int idx = tid; idx < 18 * 384; idx += REC_THREADS) {
        int k = idx % 384;
        int ru = idx / 384;
        int g = ru / 6, u = ru % 6;
        float v = Wh[((size_t)(g * 384 + u0 + u)) * 384 + k];
        Ws2[ru * WS2_STRIDE + 2 * k]     = v;
        Ws2[ru * WS2_STRIDE + 2 * k + 1] = v;
    }
    if (tid < 18) {
        int g = tid / 6, u = tid % 6;
        bh[tid] = bhh[g * 384 + u0 + u];
    }

    const float* wRp = Ws2 + (0 * 6 + ul) * WS2_STRIDE;
    const float* wZp = Ws2 + (1 * 6 + ul) * WS2_STRIDE;
    const float* wNp = Ws2 + (2 * 6 + ul) * WS2_STRIDE;

    // initial xs prefetch (s = 0)
    float xpref[6];
    {
        int t0 = dir ? (SS - 1) : 0;
#pragma unroll
        for (int e = 0; e < 6; ++e) {
            int idx = e * REC_THREADS + tid;
            int b = idx & 31;
            int ru = idx >> 5;
            int g = ru / 6, u = ru % 6;
            xpref[e] = __ldcg(&g_XW[((size_t)(dir * G3 + g * 384 + u0 + u)) * M16K + t0 * 32 + b]);
        }
    }

    int pp = 0;
    for (int s = 0; s < SS; ++s) {
        const int t = dir ? (SS - 1 - s) : s;

        // commit prefetched xs, stage H
#pragma unroll
        for (int e = 0; e < 6; ++e) xs[e * REC_THREADS + tid] = xpref[e];
        {
            const float4* src = (const float4*)(&g_H[dir][pp][0]);
            float4* dst = (float4*)Hs;
            for (int i = tid; i < (HH * BB) / 4; i += REC_THREADS)
                dst[i] = __ldcg(src + i);
        }
        __syncthreads();

        // prefetch xs for s+1 (overlaps compute)
        if (s + 1 < SS) {
            int tn = dir ? (SS - 2 - s) : (s + 1);
#pragma unroll
            for (int e = 0; e < 6; ++e) {
                int idx = e * REC_THREADS + tid;
                int b = idx & 31;
                int ru = idx >> 5;
                int g = ru / 6, u = ru % 6;
                xpref[e] = __ldcg(&g_XW[((size_t)(dir * G3 + g * 384 + u0 + u)) * M16K + tn * 32 + b]);
            }
        }

        // 3-gate dot over K=384 for 2 batches (packed f32x2)
        unsigned long long aR = pk2(bh[ul],      bh[ul]);
        unsigned long long aZ = pk2(bh[6 + ul],  bh[6 + ul]);
        unsigned long long aN = pk2(bh[12 + ul], bh[12 + ul]);
        const float* hp = Hs + 2 * p;
#pragma unroll 2
        for (int k = 0; k < 384; k += 2) {
            unsigned long long h0 = *(const unsigned long long*)(hp + k * 32);
            unsigned long long h1 = *(const unsigned long long*)(hp + (k + 1) * 32);
            ulonglong2 wr = *(const ulonglong2*)(wRp + 2 * k);
            ulonglong2 wz = *(const ulonglong2*)(wZp + 2 * k);
            ulonglong2 wn = *(const ulonglong2*)(wNp + 2 * k);
            FMA2(aR, wr.x, h0, aR); FMA2(aR, wr.y, h1, aR);
            FMA2(aZ, wz.x, h0, aZ); FMA2(aZ, wz.y, h1, aZ);
            FMA2(aN, wn.x, h0, aN); FMA2(aN, wn.y, h1, aN);
        }

        float2 gR = upk2(aR), gZ = upk2(aZ), gN = upk2(aN);
        float2 xr = *(const float2*)&xs[(0 * 6 + ul) * 32 + 2 * p];
        float2 xz = *(const float2*)&xs[(1 * 6 + ul) * 32 + 2 * p];
        float2 xn = *(const float2*)&xs[(2 * 6 + ul) * 32 + 2 * p];
        float2 hold = *(const float2*)&Hs[j * 32 + 2 * p];

        float r0 = 1.f / (1.f + expf(-(xr.x + gR.x)));
        float r1 = 1.f / (1.f + expf(-(xr.y + gR.y)));
        float z0 = 1.f / (1.f + expf(-(xz.x + gZ.x)));
        float z1 = 1.f / (1.f + expf(-(xz.y + gZ.y)));
        float n0 = tanhf(xn.x + r0 * gN.x);
        float n1 = tanhf(xn.y + r1 * gN.y);
        float h0 = n0 + z0 * (hold.x - n0);
        float h1 = n1 + z1 * (hold.y - n1);

        __stcg((float2*)&g_H[dir][pp ^ 1][j * 32 + 2 * p], make_float2(h0, h1));
        Hn[ul * 32 + 2 * p]     = h0;
        Hn[ul * 32 + 2 * p + 1] = h1;

        __threadfence();
        __syncthreads();

        // OUT write (192 elements / 96 threads)
#pragma unroll
        for (int e = 0; e < 2; ++e) {
            int idx = tid + e * REC_THREADS;
            int b2 = idx / 6, jj = idx - b2 * 6;
            g_OUT[(size_t)(t * 32 + b2) * (2 * HH) + dir * HH + u0 + jj] = Hn[jj * 32 + b2];
        }

        if (tid == 0) {
            atomicAdd(&g_bar[dir * SS + s], 1);
            volatile int* bp = &g_bar[dir * SS + s];
            while (*bp < 64) { __nanosleep(32); }
            __threadfence();
        }
        __syncthreads();
        pp ^= 1;
    }
}

// ------------------------- softmax + attention pooling ----------------------
__global__ void __launch_bounds__(256) attn_pool(float* __restrict__ out)
{
    __shared__ float sc[SS];
    __shared__ float red[256];
    const int b = blockIdx.x;
    const int tid = threadIdx.x;

    for (int t = tid; t < SS; t += 256) sc[t] = g_scores[t * 32 + b];
    __syncthreads();

    float mx = -3.4e38f;
    for (int t = tid; t < SS; t += 256) mx = fmaxf(mx, sc[t]);
    red[tid] = mx;
    __syncthreads();
    for (int sft = 128; sft > 0; sft >>= 1) {
        if (tid < sft) red[tid] = fmaxf(red[tid], red[tid + sft]);
        __syncthreads();
    }
    mx = red[0];
    __syncthreads();

    float lsum = 0.f;
    for (int t = tid; t < SS; t += 256) {
        float e = expf(sc[t] - mx);
        sc[t] = e;
        lsum += e;
    }
    red[tid] = lsum;
    __syncthreads();
    for (int sft = 128; sft > 0; sft >>= 1) {
        if (tid < sft) red[tid] += red[tid + sft];
        __syncthreads();
    }
    float inv = 1.f / red[0];
    __syncthreads();

#pragma unroll
    for (int pass = 0; pass < 3; ++pass) {
        int dd = pass * 256 + tid;
        float acc = 0.f;
#pragma unroll 4
        for (int t = 0; t < SS; ++t)
            acc = fmaf(sc[t], g_OUT[(size_t)(t * 32 + b) * (2 * HH) + dd], acc);
        out[b * (2 * HH) + dd] = acc * inv;
    }
}

// --------------------------------- launch -----------------------------------
extern "C" void kernel_launch(void* const* d_in, const int* in_sizes, int n_in,
                              void* d_out, int out_size)
{
    const float* ip   = (const float*)d_in[0];
    const float* Wihf = (const float*)d_in[1];
    const float* Whhf = (const float*)d_in[2];
    const float* bihf = (const float*)d_in[3];
    const float* bhhf = (const float*)d_in[4];
    const float* Wihb = (const float*)d_in[5];
    const float* Whhb = (const float*)d_in[6];
    const float* bihb = (const float*)d_in[7];
    const float* bhhb = (const float*)d_in[8];
    const float* Wa   = (const float*)d_in[9];
    const float* ba   = (const float*)d_in[10];
    const float* ctx  = (const float*)d_in[11];
    float* out = (float*)d_out;

    const __half *pAc, *pBc, *pWac, *pOc;
    cudaGetSymbolAddress((void**)&pAc, g_Ac);
    cudaGetSymbolAddress((void**)&pBc, g_Bc);
    cudaGetSymbolAddress((void**)&pWac, g_Wac);
    cudaGetSymbolAddress((void**)&pOc, g_Oc);

    const int rec_smem = REC_SMEM_FLOATS * 4;
    cudaFuncSetAttribute(gru_rec, cudaFuncAttributeMaxDynamicSharedMemorySize, rec_smem);
    cudaFuncSetAttribute(hgemm_kernel<0>, cudaFuncAttributeMaxDynamicSharedMemorySize, HG_DYN_SMEM);
    cudaFuncSetAttribute(hgemm_kernel<1>, cudaFuncAttributeMaxDynamicSharedMemorySize, HG_DYN_SMEM);

    init_kernel<<<64, 256>>>();
    {
        int tot = (M16K + NROWS + 2 * HH) * (DD / 4);
        convert_split<<<(tot + 255) / 256, 256>>>(ip, Wihf, Wihb, Wa);
    }
    hgemm_kernel<0><<<dim3(NROWS / 128, M16K / 128), 256, HG_DYN_SMEM>>>(
        pAc, pBc, bihf, bihb);
    gru_rec<<<128, REC_THREADS, rec_smem>>>(Whhf, Whhb, bhhf, bhhb);
    {
        int tot = M16K * (DD / 4);
        out_convert<<<(tot + 255) / 256, 256>>>();
    }
    hgemm_kernel<1><<<dim3((2 * HH) / 128, M16K / 128), 256, HG_DYN_SMEM>>>(
        pWac, pOc, ba, ctx);
    attn_pool<<<32, 256>>>(out);
}

// round 5
// speedup vs baseline: 1.4212x; 1.4212x over previous
#include <cuda_runtime.h>
#include <cuda_fp16.h>
#include <math.h>
#include <stdint.h>

#define BB   32
#define SS   512
#define DD   768
#define HH   384
#define G3   (3*HH)      // 1152
#define NROWS (2*G3)     // 2304
#define M16K (SS*BB)     // 16384
#define KC   (3*DD)      // 2304  (split-concat K)

// ---------------- scratch (static device globals; no runtime alloc) ----------
__device__ float g_XW[(size_t)NROWS * M16K];        // [n][m], m = t*32+b
__device__ float g_OUT[(size_t)M16K * (2*HH)];      // [m][768]
__device__ float g_H[2][2][HH * BB];                // [dir][buf][k*32+b]
__device__ int   g_bar[2 * SS];
__device__ float g_scores[M16K];
// fp16 split-concat operands: A = [Wh | Wh | Wl], B = [Xh | Xl | Xh]
__device__ __half g_Ac[(size_t)NROWS * KC];
__device__ __half g_Bc[(size_t)M16K  * KC];

// ============================ PTX helpers ====================================
__device__ __forceinline__ uint32_t smem_u32(const void* p) {
    uint32_t a;
    asm("{ .reg .u64 t; cvta.to.shared.u64 t, %1; cvt.u32.u64 %0, t; }"
        : "=r"(a) : "l"(p));
    return a;
}

#define CP_ASYNC16(saddr, gptr) \
    asm volatile("cp.async.cg.shared.global [%0], [%1], 16;" \
                 :: "r"(saddr), "l"(gptr) : "memory")
#define CP_COMMIT() asm volatile("cp.async.commit_group;" ::: "memory")
#define CP_WAIT2()  asm volatile("cp.async.wait_group 2;" ::: "memory")

#define LDMATRIX_X4(r0, r1, r2, r3, addr) \
    asm volatile("ldmatrix.sync.aligned.m8n8.x4.shared.b16 {%0,%1,%2,%3}, [%4];" \
                 : "=r"(r0), "=r"(r1), "=r"(r2), "=r"(r3) : "r"(addr))

#define MMA16816(c0, c1, c2, c3, a0, a1, a2, a3, b0, b1) \
    asm volatile("mma.sync.aligned.m16n8k16.row.col.f32.f16.f16.f32 " \
                 "{%0,%1,%2,%3}, {%4,%5,%6,%7}, {%8,%9}, {%0,%1,%2,%3};" \
                 : "+f"(c0), "+f"(c1), "+f"(c2), "+f"(c3) \
                 : "r"(a0), "r"(a1), "r"(a2), "r"(a3), "r"(b0), "r"(b1))

__device__ __forceinline__ void red_release_add(int* p) {
    asm volatile("red.release.gpu.global.add.u32 [%0], 1;" :: "l"(p) : "memory");
}
__device__ __forceinline__ int ld_acquire(const int* p) {
    int v;
    asm volatile("ld.acquire.gpu.global.u32 %0, [%1];" : "=r"(v) : "l"(p) : "memory");
    return v;
}

// ---------------------------------- init ------------------------------------
__global__ void init_kernel() {
    int idx = blockIdx.x * blockDim.x + threadIdx.x;
    int nthr = gridDim.x * blockDim.x;
    float* h = &g_H[0][0][0];
    for (int i = idx; i < 2 * 2 * HH * BB; i += nthr) h[i] = 0.f;
    for (int i = idx; i < 2 * SS; i += nthr) g_bar[i] = 0;
    for (int i = idx; i < M16K; i += nthr) g_scores[i] = 0.f;
}

// ---------------- fp32 -> fp16 hi/lo split + K-concat conversion -------------
__global__ void __launch_bounds__(256) convert_split(
    const float* __restrict__ ip,
    const float* __restrict__ Wf, const float* __restrict__ Wb)
{
    const int TOT = (M16K + NROWS) * (DD / 4);
    int idx = blockIdx.x * blockDim.x + threadIdx.x;
    if (idx >= TOT) return;
    int row = idx / (DD / 4);
    int k = (idx - row * (DD / 4)) * 4;

    const float* src;
    __half* dst;
    bool isA;
    if (row < M16K) {
        int b = row & 31, t = row >> 5;
        src = ip + ((size_t)(b * SS + t)) * DD + k;
        dst = g_Bc + (size_t)row * KC;
        isA = false;
    } else {
        int n = row - M16K;
        src = ((n < G3) ? (Wf + (size_t)n * DD) : (Wb + (size_t)(n - G3) * DD)) + k;
        dst = g_Ac + (size_t)n * KC;
        isA = true;
    }
    float4 v = *(const float4*)src;
    union { __half h[4]; uint2 u; } hi, lo;
    hi.h[0] = __float2half_rn(v.x); lo.h[0] = __float2half_rn(v.x - __half2float(hi.h[0]));
    hi.h[1] = __float2half_rn(v.y); lo.h[1] = __float2half_rn(v.y - __half2float(hi.h[1]));
    hi.h[2] = __float2half_rn(v.z); lo.h[2] = __float2half_rn(v.z - __half2float(hi.h[2]));
    hi.h[3] = __float2half_rn(v.w); lo.h[3] = __float2half_rn(v.w - __half2float(hi.h[3]));

    if (isA) {   // [h | h | l]
        *(uint2*)(dst + k)          = hi.u;
        *(uint2*)(dst + DD + k)     = hi.u;
        *(uint2*)(dst + 2 * DD + k) = lo.u;
    } else {     // [h | l | h]
        *(uint2*)(dst + k)          = hi.u;
        *(uint2*)(dst + DD + k)     = lo.u;
        *(uint2*)(dst + 2 * DD + k) = hi.u;
    }
}

// --------------------- HGEMM input projection (mma.sync) ---------------------
#define PROJ_STAGE_BYTES 10240          // 128 rows * 80B
#define PROJ_DYN_SMEM    (8 * PROJ_STAGE_BYTES)

__global__ void __launch_bounds__(256, 2) proj_hgemm(
    const float* __restrict__ bihf, const float* __restrict__ bihb)
{
    extern __shared__ char dyn[];
    const uint32_t Abase = smem_u32(dyn);
    const uint32_t Bbase = Abase + 4 * PROJ_STAGE_BYTES;

    const int tid  = threadIdx.x;
    const int wid  = tid >> 5, lane = tid & 31;
    const int wn   = wid >> 2;
    const int wm   = wid & 3;
    const int n0   = blockIdx.x * 128;
    const int m0   = blockIdx.y * 128;

    const int KT = KC / 32;               // 72

    auto load_stage = [&](int buf, int kt) {
        uint32_t as = Abase + buf * PROJ_STAGE_BYTES;
        uint32_t bs = Bbase + buf * PROJ_STAGE_BYTES;
#pragma unroll
        for (int i = 0; i < 2; ++i) {
            int idx = tid + i * 256;
            int row = idx >> 2, c = idx & 3;
            const __half* ga = g_Ac + (size_t)(n0 + row) * KC + kt * 32 + c * 8;
            CP_ASYNC16(as + row * 80 + c * 16, ga);
            const __half* gb = g_Bc + (size_t)(m0 + row) * KC + kt * 32 + c * 8;
            CP_ASYNC16(bs + row * 80 + c * 16, gb);
        }
        CP_COMMIT();
    };

    float acc[4][4][4];
#pragma unroll
    for (int i = 0; i < 4; i++)
#pragma unroll
        for (int j = 0; j < 4; j++)
#pragma unroll
            for (int r = 0; r < 4; r++) acc[i][j][r] = 0.f;

    load_stage(0, 0);
    load_stage(1, 1);
    load_stage(2, 2);

    const int lr = lane & 15;
    const int lc = lane >> 4;

    for (int kt = 0; kt < KT; ++kt) {
        CP_WAIT2();
        __syncthreads();
        if (kt + 3 < KT) load_stage((kt + 3) & 3, kt + 3);
        else CP_COMMIT();

        uint32_t as = Abase + (kt & 3) * PROJ_STAGE_BYTES;
        uint32_t bs = Bbase + (kt & 3) * PROJ_STAGE_BYTES;

#pragma unroll
        for (int kk = 0; kk < 2; ++kk) {
            uint32_t bfr[4][2];
#pragma unroll
            for (int bm = 0; bm < 2; ++bm) {
                uint32_t r0, r1, r2, r3;
                uint32_t addr = bs + (wm * 32 + bm * 16 + lr) * 80 + (kk * 2 + lc) * 16;
                LDMATRIX_X4(r0, r1, r2, r3, addr);
                bfr[bm * 2 + 0][0] = r0; bfr[bm * 2 + 0][1] = r2;
                bfr[bm * 2 + 1][0] = r1; bfr[bm * 2 + 1][1] = r3;
            }
#pragma unroll
            for (int fn = 0; fn < 4; ++fn) {
                uint32_t a0, a1, a2, a3;
                uint32_t addr = as + (wn * 64 + fn * 16 + lr) * 80 + (kk * 2 + lc) * 16;
                LDMATRIX_X4(a0, a1, a2, a3, addr);
#pragma unroll
                for (int fm = 0; fm < 4; ++fm) {
                    MMA16816(acc[fn][fm][0], acc[fn][fm][1], acc[fn][fm][2], acc[fn][fm][3],
                             a0, a1, a2, a3, bfr[fm][0], bfr[fm][1]);
                }
            }
        }
        __syncthreads();
    }

    float* Cs = (float*)dyn;                 // [128][136]
    const int crow = lane >> 2;
    const int ccol = 2 * (lane & 3);
#pragma unroll
    for (int fn = 0; fn < 4; ++fn) {
#pragma unroll
        for (int fm = 0; fm < 4; ++fm) {
            int r = wn * 64 + fn * 16 + crow;
            int c = wm * 32 + fm * 8 + ccol;
            Cs[r * 136 + c]           = acc[fn][fm][0];
            Cs[r * 136 + c + 1]       = acc[fn][fm][1];
            Cs[(r + 8) * 136 + c]     = acc[fn][fm][2];
            Cs[(r + 8) * 136 + c + 1] = acc[fn][fm][3];
        }
    }
    __syncthreads();

#pragma unroll
    for (int it = 0; it < 16; ++it) {
        int idx = tid + it * 256;
        int row = idx >> 5, cq = idx & 31;
        int n = n0 + row;
        float bv = (n < G3) ? __ldg(bihf + n) : __ldg(bihb + n - G3);
        float4 v;
        v.x = Cs[row * 136 + cq * 4 + 0] + bv;
        v.y = Cs[row * 136 + cq * 4 + 1] + bv;
        v.z = Cs[row * 136 + cq * 4 + 2] + bv;
        v.w = Cs[row * 136 + cq * 4 + 3] + bv;
        *(float4*)&g_XW[(size_t)n * M16K + m0 + cq * 4] = v;
    }
}

// ---------------------------- GRU recurrence --------------------------------
// 128 CTAs: 64/dir, 6 units each. 384 threads = 12 warps (3/SMSP), k-split x2:
// warps 0-5: units 0-5, k in [0,192); warps 6-11: units 0-5, k in [192,384).
// smem floats: Ws 6912 | Hs 12288 | xs 576 | bh 32 | Hn 192 | part 576
#define REC_THREADS 384
#define REC_SMEM_FLOATS (6912 + 12288 + 576 + 32 + 192 + 576)

__global__ void __launch_bounds__(REC_THREADS) gru_rec(
    const float* __restrict__ Whf, const float* __restrict__ Whb,
    const float* __restrict__ bhf, const float* __restrict__ bhb)
{
    extern __shared__ float sm[];
    float* Ws   = sm;                  // 6912
    float* Hs   = sm + 6912;           // 12288
    float* xs   = Hs + 12288;          // 576
    float* bh   = xs + 576;            // 32
    float* Hn   = bh + 32;             // 192
    float* part = Hn + 192;            // 576 (3 x 192)

    const int bid = blockIdx.x;
    const int dir = bid >> 6;
    const int u0  = (bid & 63) * 6;
    const int tid = threadIdx.x;
    const int kh  = (tid >= 192) ? 1 : 0;
    const int r   = tid - kh * 192;        // 0..191
    const int w   = r >> 5;                // unit 0..5
    const int lane = r & 31;               // batch
    const int kbase = kh * 192;
    const int j   = u0 + w;

    const float* Wh  = dir ? Whb : Whf;
    const float* bhh = dir ? bhb : bhf;

    for (int idx = tid; idx < 18 * 384; idx += REC_THREADS) {
        int k = idx % 384;
        int ru = idx / 384;
        int g = ru / 6, u = ru % 6;
        Ws[idx] = Wh[((size_t)(g * 384 + u0 + u)) * 384 + k];
    }
    if (tid < 18) {
        int g = tid / 6, u = tid % 6;
        bh[tid] = bhh[g * 384 + u0 + u];
    }

    const float* wR = Ws + (0 * 6 + w) * 384 + kbase;
    const float* wZ = Ws + (1 * 6 + w) * 384 + kbase;
    const float* wN = Ws + (2 * 6 + w) * 384 + kbase;

    // initial xs prefetch (s = 0); 576 entries, e0: all, e1: tid<192
    float xpref[2];
    {
        int t0 = dir ? (SS - 1) : 0;
        {
            int idx = tid;
            int b = idx & 31, ru = idx >> 5;
            int g = ru / 6, u = ru % 6;
            xpref[0] = __ldcg(&g_XW[((size_t)(dir * G3 + g * 384 + u0 + u)) * M16K + t0 * 32 + b]);
        }
        if (tid < 192) {
            int idx = tid + 384;
            int b = idx & 31, ru = idx >> 5;
            int g = ru / 6, u = ru % 6;
            xpref[1] = __ldcg(&g_XW[((size_t)(dir * G3 + g * 384 + u0 + u)) * M16K + t0 * 32 + b]);
        }
    }

    int pp = 0;
    for (int s = 0; s < SS; ++s) {
        const int t = dir ? (SS - 1 - s) : s;

        // commit prefetched xs; stage H (L2-coherent, 48KB, 8 float4/thread)
        xs[tid] = xpref[0];
        if (tid < 192) xs[tid + 384] = xpref[1];
        {
            const float4* src = (const float4*)(&g_H[dir][pp][0]);
            float4* dst = (float4*)Hs;
#pragma unroll
            for (int i = 0; i < 8; ++i)
                dst[tid + i * REC_THREADS] = __ldcg(src + tid + i * REC_THREADS);
        }
        __syncthreads();

        // prefetch next step's xs (overlaps compute)
        if (s + 1 < SS) {
            int tn = dir ? (SS - 2 - s) : (s + 1);
            {
                int idx = tid;
                int b = idx & 31, ru = idx >> 5;
                int g = ru / 6, u = ru % 6;
                xpref[0] = __ldcg(&g_XW[((size_t)(dir * G3 + g * 384 + u0 + u)) * M16K + tn * 32 + b]);
            }
            if (tid < 192) {
                int idx = tid + 384;
                int b = idx & 31, ru = idx >> 5;
                int g = ru / 6, u = ru % 6;
                xpref[1] = __ldcg(&g_XW[((size_t)(dir * G3 + g * 384 + u0 + u)) * M16K + tn * 32 + b]);
            }
        }

        // half-K 3-gate dot (192 k per thread)
        float aR = kh ? 0.f : bh[w];
        float aZ = kh ? 0.f : bh[6 + w];
        float aN = kh ? 0.f : bh[12 + w];
#pragma unroll 4
        for (int k4 = 0; k4 < 48; ++k4) {
            float4 r4 = *(const float4*)(wR + 4 * k4);
            float4 z4 = *(const float4*)(wZ + 4 * k4);
            float4 n4 = *(const float4*)(wN + 4 * k4);
            const float* hp = Hs + (kbase + 4 * k4) * 32 + lane;
            float h0 = hp[0], h1 = hp[32], h2 = hp[64], h3 = hp[96];
            aR = fmaf(r4.x, h0, aR); aR = fmaf(r4.y, h1, aR);
            aR = fmaf(r4.z, h2, aR); aR = fmaf(r4.w, h3, aR);
            aZ = fmaf(z4.x, h0, aZ); aZ = fmaf(z4.y, h1, aZ);
            aZ = fmaf(z4.z, h2, aZ); aZ = fmaf(z4.w, h3, aZ);
            aN = fmaf(n4.x, h0, aN); aN = fmaf(n4.y, h1, aN);
            aN = fmaf(n4.z, h2, aN); aN = fmaf(n4.w, h3, aN);
        }
        if (kh) {
            part[r]       = aR;
            part[192 + r] = aZ;
            part[384 + r] = aN;
        }
        __syncthreads();

        if (!kh) {
            aR += part[r];
            aZ += part[192 + r];
            aN += part[384 + r];
            float xr = xs[(0 * 6 + w) * 32 + lane];
            float xz = xs[(1 * 6 + w) * 32 + lane];
            float xn = xs[(2 * 6 + w) * 32 + lane];
            float rg = 1.f / (1.f + expf(-(xr + aR)));
            float zg = 1.f / (1.f + expf(-(xz + aZ)));
            float ng = tanhf(xn + rg * aN);
            float hold = Hs[j * 32 + lane];
            float hnew = ng + zg * (hold - ng);
            __stcg(&g_H[dir][pp ^ 1][j * 32 + lane], hnew);
            Hn[w * 32 + lane] = hnew;
        }
        __syncthreads();

        // release-arrive: publishes this CTA's H stores (ordered by syncthreads)
        if (tid == 0) red_release_add(&g_bar[dir * SS + s]);

        // OUT writes — off the critical path (visibility via kernel boundary)
        if (tid < 192) {
            int b2 = tid / 6, jj = tid - b2 * 6;
            g_OUT[(size_t)(t * 32 + b2) * (2 * HH) + dir * HH + u0 + jj] = Hn[jj * 32 + b2];
        }

        if (tid == 0) {
            while (ld_acquire(&g_bar[dir * SS + s]) < 64) __nanosleep(32);
        }
        __syncthreads();
        pp ^= 1;
    }
}

// -------------------- attention scores GEMM (fused epilogue) ----------------
__global__ void __launch_bounds__(256) attn_gemm(
    const float* __restrict__ Wa, const float* __restrict__ ba,
    const float* __restrict__ ctx)
{
    __shared__ float As[2][8][128];
    __shared__ float Bs[2][8][128];
    const int tid = threadIdx.x;
    const int m0 = blockIdx.x * 128;
    const int n0 = blockIdx.y * 128;
    const int tx = tid & 15, ty = tid >> 4;

    const int l_row = tid >> 1;
    const int l_col = (tid & 1) * 4;
    const float* Aptr = g_OUT + (size_t)(m0 + l_row) * (2 * HH);
    const float* Bptr = Wa + (size_t)(n0 + l_row) * (2 * HH);

    float acc[8][8];
#pragma unroll
    for (int i = 0; i < 8; i++)
#pragma unroll
        for (int jj = 0; jj < 8; jj++) acc[i][jj] = 0.f;

    float4 aR = *(const float4*)(Aptr + l_col);
    float4 bR = *(const float4*)(Bptr + l_col);
    As[0][l_col + 0][l_row] = aR.x; As[0][l_col + 1][l_row] = aR.y;
    As[0][l_col + 2][l_row] = aR.z; As[0][l_col + 3][l_row] = aR.w;
    Bs[0][l_col + 0][l_row] = bR.x; Bs[0][l_col + 1][l_row] = bR.y;
    Bs[0][l_col + 2][l_row] = bR.z; Bs[0][l_col + 3][l_row] = bR.w;
    __syncthreads();

    const int KT = (2 * HH) / 8;
    for (int kt = 0; kt < KT; ++kt) {
        int cur = kt & 1;
        if (kt < KT - 1) {
            aR = *(const float4*)(Aptr + (kt + 1) * 8 + l_col);
            bR = *(const float4*)(Bptr + (kt + 1) * 8 + l_col);
        }
#pragma unroll
        for (int kk = 0; kk < 8; ++kk) {
            float a0[8], b0[8];
            *(float4*)(a0)     = *(const float4*)&As[cur][kk][ty * 8];
            *(float4*)(a0 + 4) = *(const float4*)&As[cur][kk][ty * 8 + 4];
            *(float4*)(b0)     = *(const float4*)&Bs[cur][kk][tx * 8];
            *(float4*)(b0 + 4) = *(const float4*)&Bs[cur][kk][tx * 8 + 4];
#pragma unroll
            for (int i = 0; i < 8; i++)
#pragma unroll
                for (int jj = 0; jj < 8; jj++)
                    acc[i][jj] = fmaf(a0[i], b0[jj], acc[i][jj]);
        }
        if (kt < KT - 1) {
            int nx = cur ^ 1;
            As[nx][l_col + 0][l_row] = aR.x; As[nx][l_col + 1][l_row] = aR.y;
            As[nx][l_col + 2][l_row] = aR.z; As[nx][l_col + 3][l_row] = aR.w;
            Bs[nx][l_col + 0][l_row] = bR.x; Bs[nx][l_col + 1][l_row] = bR.y;
            Bs[nx][l_col + 2][l_row] = bR.z; Bs[nx][l_col + 3][l_row] = bR.w;
        }
        __syncthreads();
    }

#pragma unroll
    for (int i = 0; i < 8; i++) {
        float partial = 0.f;
#pragma unroll
        for (int jj = 0; jj < 8; jj++) {
            int n = n0 + tx * 8 + jj;
            partial += tanhf(acc[i][jj] + ba[n]) * ctx[n];
        }
        atomicAdd(&g_scores[m0 + ty * 8 + i], partial);
    }
}

// ------------------------- softmax + attention pooling ----------------------
__global__ void __launch_bounds__(256) attn_pool(float* __restrict__ out)
{
    __shared__ float sc[SS];
    __shared__ float red[256];
    const int b = blockIdx.x;
    const int tid = threadIdx.x;

    for (int t = tid; t < SS; t += 256) sc[t] = g_scores[t * 32 + b];
    __syncthreads();

    float mx = -3.4e38f;
    for (int t = tid; t < SS; t += 256) mx = fmaxf(mx, sc[t]);
    red[tid] = mx;
    __syncthreads();
    for (int sft = 128; sft > 0; sft >>= 1) {
        if (tid < sft) red[tid] = fmaxf(red[tid], red[tid + sft]);
        __syncthreads();
    }
    mx = red[0];
    __syncthreads();

    float lsum = 0.f;
    for (int t = tid; t < SS; t += 256) {
        float e = expf(sc[t] - mx);
        sc[t] = e;
        lsum += e;
    }
    red[tid] = lsum;
    __syncthreads();
    for (int sft = 128; sft > 0; sft >>= 1) {
        if (tid < sft) red[tid] += red[tid + sft];
        __syncthreads();
    }
    float inv = 1.f / red[0];
    __syncthreads();

#pragma unroll
    for (int pass = 0; pass < 3; ++pass) {
        int dd = pass * 256 + tid;
        float acc = 0.f;
#pragma unroll 4
        for (int t = 0; t < SS; ++t)
            acc = fmaf(sc[t], g_OUT[(size_t)(t * 32 + b) * (2 * HH) + dd], acc);
        out[b * (2 * HH) + dd] = acc * inv;
    }
}

// --------------------------------- launch -----------------------------------
extern "C" void kernel_launch(void* const* d_in, const int* in_sizes, int n_in,
                              void* d_out, int out_size)
{
    const float* ip   = (const float*)d_in[0];
    const float* Wihf = (const float*)d_in[1];
    const float* Whhf = (const float*)d_in[2];
    const float* bihf = (const float*)d_in[3];
    const float* bhhf = (const float*)d_in[4];
    const float* Wihb = (const float*)d_in[5];
    const float* Whhb = (const float*)d_in[6];
    const float* bihb = (const float*)d_in[7];
    const float* bhhb = (const float*)d_in[8];
    const float* Wa   = (const float*)d_in[9];
    const float* ba   = (const float*)d_in[10];
    const float* ctx  = (const float*)d_in[11];
    float* out = (float*)d_out;

    const int rec_smem = REC_SMEM_FLOATS * 4;   // 82336 bytes
    cudaFuncSetAttribute(gru_rec, cudaFuncAttributeMaxDynamicSharedMemorySize, rec_smem);
    cudaFuncSetAttribute(proj_hgemm, cudaFuncAttributeMaxDynamicSharedMemorySize, PROJ_DYN_SMEM);

    init_kernel<<<64, 256>>>();
    {
        int tot = (M16K + NROWS) * (DD / 4);
        convert_split<<<(tot + 255) / 256, 256>>>(ip, Wihf, Wihb);
    }
    proj_hgemm<<<dim3(NROWS / 128, M16K / 128), 256, PROJ_DYN_SMEM>>>(bihf, bihb);
    gru_rec<<<128, REC_THREADS, rec_smem>>>(Whhf, Whhb, bhhf, bhhb);
    attn_gemm<<<dim3(M16K / 128, (2 * HH) / 128), 256>>>(Wa, ba, ctx);
    attn_pool<<<32, 256>>>(out);
}

// round 6
// speedup vs baseline: 1.5674x; 1.1029x over previous
#include <cuda_runtime.h>
#include <cuda_fp16.h>
#include <math.h>
#include <stdint.h>

#define BB   32
#define SS   512
#define DD   768
#define HH   384
#define G3   (3*HH)      // 1152
#define NROWS (2*G3)     // 2304
#define M16K (SS*BB)     // 16384
#define KC   (3*DD)      // 2304  (split-concat K)

// ---------------- scratch (static device globals; no runtime alloc) ----------
__device__ float g_XW[(size_t)NROWS * M16K];        // [n][m], m = t*32+b
__device__ float g_OUT[(size_t)M16K * (2*HH)];      // [m][768]
__device__ float g_H[2][2][HH * BB];                // [dir][buf][k*32+b]
__device__ int   g_bar[2 * SS];
__device__ float g_scores[M16K];
// fp16 split-concat operands
__device__ __half g_Ac [(size_t)NROWS * KC];        // proj A: [Wh|Wh|Wl]
__device__ __half g_Bc [(size_t)M16K  * KC];        // proj B: [Xh|Xl|Xh]
__device__ __half g_Wac[(size_t)(2*HH) * KC];       // attn A: [Wah|Wah|Wal]
__device__ __half g_Oc [(size_t)M16K  * KC];        // attn B: [Oh|Ol|Oh]

// ============================ PTX helpers ====================================
__device__ __forceinline__ uint32_t smem_u32(const void* p) {
    uint32_t a;
    asm("{ .reg .u64 t; cvta.to.shared.u64 t, %1; cvt.u32.u64 %0, t; }"
        : "=r"(a) : "l"(p));
    return a;
}

#define CP_ASYNC16(saddr, gptr) \
    asm volatile("cp.async.cg.shared.global [%0], [%1], 16;" \
                 :: "r"(saddr), "l"(gptr) : "memory")
#define CP_COMMIT() asm volatile("cp.async.commit_group;" ::: "memory")
#define CP_WAIT2()  asm volatile("cp.async.wait_group 2;" ::: "memory")

#define LDMATRIX_X4(r0, r1, r2, r3, addr) \
    asm volatile("ldmatrix.sync.aligned.m8n8.x4.shared.b16 {%0,%1,%2,%3}, [%4];" \
                 : "=r"(r0), "=r"(r1), "=r"(r2), "=r"(r3) : "r"(addr))

#define MMA16816(c0, c1, c2, c3, a0, a1, a2, a3, b0, b1) \
    asm volatile("mma.sync.aligned.m16n8k16.row.col.f32.f16.f16.f32 " \
                 "{%0,%1,%2,%3}, {%4,%5,%6,%7}, {%8,%9}, {%0,%1,%2,%3};" \
                 : "+f"(c0), "+f"(c1), "+f"(c2), "+f"(c3) \
                 : "r"(a0), "r"(a1), "r"(a2), "r"(a3), "r"(b0), "r"(b1))

__device__ __forceinline__ void red_release_add(int* p) {
    asm volatile("red.release.gpu.global.add.u32 [%0], 1;" :: "l"(p) : "memory");
}
__device__ __forceinline__ int ld_acquire(const int* p) {
    int v;
    asm volatile("ld.acquire.gpu.global.u32 %0, [%1];" : "=r"(v) : "l"(p) : "memory");
    return v;
}

// packed fp32x2
__device__ __forceinline__ unsigned long long pk2(float a, float b) {
    unsigned long long r;
    asm("mov.b64 %0, {%1, %2};" : "=l"(r) : "f"(a), "f"(b));
    return r;
}
__device__ __forceinline__ float2 upk2(unsigned long long v) {
    float2 f;
    asm("mov.b64 {%0, %1}, %2;" : "=f"(f.x), "=f"(f.y) : "l"(v));
    return f;
}
#define FMA2(d, a, b, c) \
    asm("fma.rn.f32x2 %0, %1, %2, %3;" : "=l"(d) : "l"(a), "l"(b), "l"(c))

// ---------------------------------- init ------------------------------------
__global__ void init_kernel() {
    int idx = blockIdx.x * blockDim.x + threadIdx.x;
    int nthr = gridDim.x * blockDim.x;
    float* h = &g_H[0][0][0];
    for (int i = idx; i < 2 * 2 * HH * BB; i += nthr) h[i] = 0.f;
    for (int i = idx; i < 2 * SS; i += nthr) g_bar[i] = 0;
    for (int i = idx; i < M16K; i += nthr) g_scores[i] = 0.f;
}

// ---------------- fp32 -> fp16 hi/lo split + K-concat conversion -------------
__global__ void __launch_bounds__(256) convert_split(
    const float* __restrict__ ip,
    const float* __restrict__ Wf, const float* __restrict__ Wb,
    const float* __restrict__ Wa)
{
    const int TOT = (M16K + NROWS + 2 * HH) * (DD / 4);
    int idx = blockIdx.x * blockDim.x + threadIdx.x;
    if (idx >= TOT) return;
    int row = idx / (DD / 4);
    int k = (idx - row * (DD / 4)) * 4;

    const float* src;
    __half* dst;
    bool isA;
    if (row < M16K) {
        int b = row & 31, t = row >> 5;
        src = ip + ((size_t)(b * SS + t)) * DD + k;
        dst = g_Bc + (size_t)row * KC;
        isA = false;
    } else if (row < M16K + NROWS) {
        int n = row - M16K;
        src = ((n < G3) ? (Wf + (size_t)n * DD) : (Wb + (size_t)(n - G3) * DD)) + k;
        dst = g_Ac + (size_t)n * KC;
        isA = true;
    } else {
        int n = row - M16K - NROWS;
        src = Wa + (size_t)n * (2 * HH) + k;
        dst = g_Wac + (size_t)n * KC;
        isA = true;
    }
    float4 v = *(const float4*)src;
    union { __half h[4]; uint2 u; } hi, lo;
    hi.h[0] = __float2half_rn(v.x); lo.h[0] = __float2half_rn(v.x - __half2float(hi.h[0]));
    hi.h[1] = __float2half_rn(v.y); lo.h[1] = __float2half_rn(v.y - __half2float(hi.h[1]));
    hi.h[2] = __float2half_rn(v.z); lo.h[2] = __float2half_rn(v.z - __half2float(hi.h[2]));
    hi.h[3] = __float2half_rn(v.w); lo.h[3] = __float2half_rn(v.w - __half2float(hi.h[3]));

    if (isA) {   // [h | h | l]
        *(uint2*)(dst + k)          = hi.u;
        *(uint2*)(dst + DD + k)     = hi.u;
        *(uint2*)(dst + 2 * DD + k) = lo.u;
    } else {     // [h | l | h]
        *(uint2*)(dst + k)          = hi.u;
        *(uint2*)(dst + DD + k)     = lo.u;
        *(uint2*)(dst + 2 * DD + k) = hi.u;
    }
}

// -------------------- OUT fp32 -> fp16 split-concat (for attn HGEMM) --------
__global__ void __launch_bounds__(256) out_convert() {
    int idx = blockIdx.x * blockDim.x + threadIdx.x;
    if (idx >= M16K * (DD / 4)) return;
    int m = idx / (DD / 4);
    int k = (idx - m * (DD / 4)) * 4;
    float4 v = *(const float4*)&g_OUT[(size_t)m * (2 * HH) + k];
    union { __half h[4]; uint2 u; } hi, lo;
    hi.h[0] = __float2half_rn(v.x); lo.h[0] = __float2half_rn(v.x - __half2float(hi.h[0]));
    hi.h[1] = __float2half_rn(v.y); lo.h[1] = __float2half_rn(v.y - __half2float(hi.h[1]));
    hi.h[2] = __float2half_rn(v.z); lo.h[2] = __float2half_rn(v.z - __half2float(hi.h[2]));
    hi.h[3] = __float2half_rn(v.w); lo.h[3] = __float2half_rn(v.w - __half2float(hi.h[3]));
    __half* dst = g_Oc + (size_t)m * KC;
    *(uint2*)(dst + k)          = hi.u;   // [h | l | h]
    *(uint2*)(dst + DD + k)     = lo.u;
    *(uint2*)(dst + 2 * DD + k) = hi.u;
}

// ----------------------- shared HGEMM (mma.sync) -----------------------------
// C[n 128][m 128] = A[n][K=2304] * B[m][K]^T. 8 warps = 2(n) x 4(m).
#define HG_STAGE_BYTES 10240            // 128 rows * 80B
#define HG_DYN_SMEM    (8 * HG_STAGE_BYTES)

template <int MODE>
__global__ void __launch_bounds__(256, 2) hgemm_kernel(
    const __half* __restrict__ Ag, const __half* __restrict__ Bg,
    const float* __restrict__ e0, const float* __restrict__ e1)
{
    extern __shared__ char dyn[];
    const uint32_t Abase = smem_u32(dyn);
    const uint32_t Bbase = Abase + 4 * HG_STAGE_BYTES;

    const int tid  = threadIdx.x;
    const int wid  = tid >> 5, lane = tid & 31;
    const int wn   = wid >> 2;
    const int wm   = wid & 3;
    const int n0   = blockIdx.x * 128;
    const int m0   = blockIdx.y * 128;

    const int KT = KC / 32;               // 72

    auto load_stage = [&](int buf, int kt) {
        uint32_t as = Abase + buf * HG_STAGE_BYTES;
        uint32_t bs = Bbase + buf * HG_STAGE_BYTES;
#pragma unroll
        for (int i = 0; i < 2; ++i) {
            int idx = tid + i * 256;
            int row = idx >> 2, c = idx & 3;
            const __half* ga = Ag + (size_t)(n0 + row) * KC + kt * 32 + c * 8;
            CP_ASYNC16(as + row * 80 + c * 16, ga);
            const __half* gb = Bg + (size_t)(m0 + row) * KC + kt * 32 + c * 8;
            CP_ASYNC16(bs + row * 80 + c * 16, gb);
        }
        CP_COMMIT();
    };

    float acc[4][4][4];
#pragma unroll
    for (int i = 0; i < 4; i++)
#pragma unroll
        for (int j = 0; j < 4; j++)
#pragma unroll
            for (int r = 0; r < 4; r++) acc[i][j][r] = 0.f;

    load_stage(0, 0);
    load_stage(1, 1);
    load_stage(2, 2);

    const int lr = lane & 15;
    const int lc = lane >> 4;

    for (int kt = 0; kt < KT; ++kt) {
        CP_WAIT2();
        __syncthreads();
        if (kt + 3 < KT) load_stage((kt + 3) & 3, kt + 3);
        else CP_COMMIT();

        uint32_t as = Abase + (kt & 3) * HG_STAGE_BYTES;
        uint32_t bs = Bbase + (kt & 3) * HG_STAGE_BYTES;

#pragma unroll
        for (int kk = 0; kk < 2; ++kk) {
            uint32_t bfr[4][2];
#pragma unroll
            for (int bm = 0; bm < 2; ++bm) {
                uint32_t r0, r1, r2, r3;
                uint32_t addr = bs + (wm * 32 + bm * 16 + lr) * 80 + (kk * 2 + lc) * 16;
                LDMATRIX_X4(r0, r1, r2, r3, addr);
                bfr[bm * 2 + 0][0] = r0; bfr[bm * 2 + 0][1] = r2;
                bfr[bm * 2 + 1][0] = r1; bfr[bm * 2 + 1][1] = r3;
            }
#pragma unroll
            for (int fn = 0; fn < 4; ++fn) {
                uint32_t a0, a1, a2, a3;
                uint32_t addr = as + (wn * 64 + fn * 16 + lr) * 80 + (kk * 2 + lc) * 16;
                LDMATRIX_X4(a0, a1, a2, a3, addr);
#pragma unroll
                for (int fm = 0; fm < 4; ++fm) {
                    MMA16816(acc[fn][fm][0], acc[fn][fm][1], acc[fn][fm][2], acc[fn][fm][3],
                             a0, a1, a2, a3, bfr[fm][0], bfr[fm][1]);
                }
            }
        }
        __syncthreads();
    }

    if (MODE == 0) {
        float* Cs = (float*)dyn;             // [128][136]
        const int crow = lane >> 2;
        const int ccol = 2 * (lane & 3);
#pragma unroll
        for (int fn = 0; fn < 4; ++fn) {
#pragma unroll
            for (int fm = 0; fm < 4; ++fm) {
                int r = wn * 64 + fn * 16 + crow;
                int c = wm * 32 + fm * 8 + ccol;
                Cs[r * 136 + c]           = acc[fn][fm][0];
                Cs[r * 136 + c + 1]       = acc[fn][fm][1];
                Cs[(r + 8) * 136 + c]     = acc[fn][fm][2];
                Cs[(r + 8) * 136 + c + 1] = acc[fn][fm][3];
            }
        }
        __syncthreads();
#pragma unroll
        for (int it = 0; it < 16; ++it) {
            int idx = tid + it * 256;
            int row = idx >> 5, cq = idx & 31;
            int n = n0 + row;
            float bv = (n < G3) ? __ldg(e0 + n) : __ldg(e1 + n - G3);
            float4 v;
            v.x = Cs[row * 136 + cq * 4 + 0] + bv;
            v.y = Cs[row * 136 + cq * 4 + 1] + bv;
            v.z = Cs[row * 136 + cq * 4 + 2] + bv;
            v.w = Cs[row * 136 + cq * 4 + 3] + bv;
            *(float4*)&g_XW[(size_t)n * M16K + m0 + cq * 4] = v;
        }
    } else {
        float* Msum = (float*)dyn;           // [128]
        if (tid < 128) Msum[tid] = 0.f;
        __syncthreads();
        const int crow = lane >> 2;
        const int ccol = 2 * (lane & 3);
#pragma unroll
        for (int fm = 0; fm < 4; ++fm) {
            int c = wm * 32 + fm * 8 + ccol;
            float s0 = 0.f, s1 = 0.f;
#pragma unroll
            for (int fn = 0; fn < 4; ++fn) {
                int na = n0 + wn * 64 + fn * 16 + crow;
                int nb = na + 8;
                float ba_a = __ldg(e0 + na), ba_b = __ldg(e0 + nb);
                float cx_a = __ldg(e1 + na), cx_b = __ldg(e1 + nb);
                s0 += tanhf(acc[fn][fm][0] + ba_a) * cx_a
                    + tanhf(acc[fn][fm][2] + ba_b) * cx_b;
                s1 += tanhf(acc[fn][fm][1] + ba_a) * cx_a
                    + tanhf(acc[fn][fm][3] + ba_b) * cx_b;
            }
            atomicAdd(&Msum[c], s0);
            atomicAdd(&Msum[c + 1], s1);
        }
        __syncthreads();
        if (tid < 128) atomicAdd(&g_scores[m0 + tid], Msum[tid]);
    }
}

// ---------------------------- GRU recurrence (FFMA2) -------------------------
// 128 CTAs: 64/dir, 6 units each. 384 threads = 12 warps = 3 unit-groups x 4 kq.
// warp w: ug = w % 3 (units 2ug, 2ug+1), kq = w / 3 (k in [kq*96, kq*96+96)).
// lane: uu = lane>>4 (unit in group), p = lane&15 (batch pair -> batches 2p, 2p+1).
// smem floats: Ws2 18x772 | Hs 12288 | xs 576 | bh 32 | Hn 192 | parts 1728
#define REC_THREADS 384
#define WS2_STRIDE  772
#define REC_SMEM_FLOATS (18*WS2_STRIDE + 12288 + 576 + 32 + 192 + 1728)

__global__ void __launch_bounds__(REC_THREADS) gru_rec(
    const float* __restrict__ Whf, const float* __restrict__ Whb,
    const float* __restrict__ bhf, const float* __restrict__ bhb)
{
    extern __shared__ float sm[];
    float* Ws2   = sm;                         // 13896
    float* Hs    = sm + 18 * WS2_STRIDE;       // 12288
    float* xs    = Hs + 12288;                 // 576
    float* bh    = xs + 576;                   // 32
    float* Hn    = bh + 32;                    // 192
    float* parts = Hn + 192;                   // 1728 = 3 kq x 3 gates x 192

    const int bid = blockIdx.x;
    const int dir = bid >> 6;
    const int u0  = (bid & 63) * 6;
    const int tid = threadIdx.x;
    const int w    = tid >> 5, lane = tid & 31;
    const int ug   = w % 3;
    const int kq   = w / 3;
    const int uu   = lane >> 4;
    const int p    = lane & 15;
    const int ul   = 2 * ug + uu;              // local unit 0..5
    const int k0   = kq * 96;
    const int j    = u0 + ul;
    const int slot = ul * 32 + 2 * p;          // output slot (2 floats)

    const float* Wh  = dir ? Whb : Whf;
    const float* bhh = dir ? bhb : bhf;

    // pair-duplicated weights: Ws2[ru*772 + 2k{,+1}] = W_hh[g*384+u0+u][k]
    for (int idx = tid; idx < 18 * 384; idx += REC_THREADS) {
        int k = idx % 384;
        int ru = idx / 384;
        int g = ru / 6, u = ru % 6;
        float v = Wh[((size_t)(g * 384 + u0 + u)) * 384 + k];
        Ws2[ru * WS2_STRIDE + 2 * k]     = v;
        Ws2[ru * WS2_STRIDE + 2 * k + 1] = v;
    }
    if (tid < 18) {
        int g = tid / 6, u = tid % 6;
        bh[tid] = bhh[g * 384 + u0 + u];
    }

    const float* wRp = Ws2 + (0 * 6 + ul) * WS2_STRIDE + 2 * k0;
    const float* wZp = Ws2 + (1 * 6 + ul) * WS2_STRIDE + 2 * k0;
    const float* wNp = Ws2 + (2 * 6 + ul) * WS2_STRIDE + 2 * k0;

    // initial xs prefetch (s = 0)
    float xpref[2];
    {
        int t0 = dir ? (SS - 1) : 0;
        {
            int idx = tid;
            int b = idx & 31, ru = idx >> 5;
            int g = ru / 6, u = ru % 6;
            xpref[0] = __ldcg(&g_XW[((size_t)(dir * G3 + g * 384 + u0 + u)) * M16K + t0 * 32 + b]);
        }
        if (tid < 192) {
            int idx = tid + 384;
            int b = idx & 31, ru = idx >> 5;
            int g = ru / 6, u = ru % 6;
            xpref[1] = __ldcg(&g_XW[((size_t)(dir * G3 + g * 384 + u0 + u)) * M16K + t0 * 32 + b]);
        }
    }

    int pp = 0;
    for (int s = 0; s < SS; ++s) {
        const int t = dir ? (SS - 1 - s) : s;

        xs[tid] = xpref[0];
        if (tid < 192) xs[tid + 384] = xpref[1];
        {
            const float4* src = (const float4*)(&g_H[dir][pp][0]);
            float4* dst = (float4*)Hs;
#pragma unroll
            for (int i = 0; i < 8; ++i)
                dst[tid + i * REC_THREADS] = __ldcg(src + tid + i * REC_THREADS);
        }
        __syncthreads();

        // prefetch next step's xs (overlaps compute)
        if (s + 1 < SS) {
            int tn = dir ? (SS - 2 - s) : (s + 1);
            {
                int idx = tid;
                int b = idx & 31, ru = idx >> 5;
                int g = ru / 6, u = ru % 6;
                xpref[0] = __ldcg(&g_XW[((size_t)(dir * G3 + g * 384 + u0 + u)) * M16K + tn * 32 + b]);
            }
            if (tid < 192) {
                int idx = tid + 384;
                int b = idx & 31, ru = idx >> 5;
                int g = ru / 6, u = ru % 6;
                xpref[1] = __ldcg(&g_XW[((size_t)(dir * G3 + g * 384 + u0 + u)) * M16K + tn * 32 + b]);
            }
        }

        // quarter-K 3-gate dot, 2 batches per lane (FFMA2)
        unsigned long long aR, aZ, aN;
        if (kq == 0) {
            aR = pk2(bh[ul], bh[ul]);
            aZ = pk2(bh[6 + ul], bh[6 + ul]);
            aN = pk2(bh[12 + ul], bh[12 + ul]);
        } else {
            aR = aZ = aN = pk2(0.f, 0.f);
        }
        const float* hp = Hs + k0 * 32 + 2 * p;
#pragma unroll 4
        for (int kk = 0; kk < 96; kk += 2) {
            unsigned long long h0 = *(const unsigned long long*)(hp + kk * 32);
            unsigned long long h1 = *(const unsigned long long*)(hp + (kk + 1) * 32);
            ulonglong2 wr = *(const ulonglong2*)(wRp + 2 * kk);
            ulonglong2 wz = *(const ulonglong2*)(wZp + 2 * kk);
            ulonglong2 wn = *(const ulonglong2*)(wNp + 2 * kk);
            FMA2(aR, wr.x, h0, aR); FMA2(aR, wr.y, h1, aR);
            FMA2(aZ, wz.x, h0, aZ); FMA2(aZ, wz.y, h1, aZ);
            FMA2(aN, wn.x, h0, aN); FMA2(aN, wn.y, h1, aN);
        }

        if (kq > 0) {
            float* pb = parts + ((kq - 1) * 3) * 192;
            *(float2*)&pb[0 * 192 * 3 ? 0 : 0 + slot]       = upk2(aR);   // gate 0
            *(float2*)&pb[192 + slot]                        = upk2(aZ);   // gate 1
            *(float2*)&pb[384 + slot]                        = upk2(aN);   // gate 2
        }
        __syncthreads();

        if (kq == 0) {
            float2 fR = upk2(aR), fZ = upk2(aZ), fN = upk2(aN);
#pragma unroll
            for (int q = 0; q < 3; ++q) {
                const float* pb = parts + (q * 3) * 192;
                float2 r2 = *(const float2*)&pb[slot];
                float2 z2 = *(const float2*)&pb[192 + slot];
                float2 n2 = *(const float2*)&pb[384 + slot];
                fR.x += r2.x; fR.y += r2.y;
                fZ.x += z2.x; fZ.y += z2.y;
                fN.x += n2.x; fN.y += n2.y;
            }
            float2 xr = *(const float2*)&xs[(0 * 6 + ul) * 32 + 2 * p];
            float2 xz = *(const float2*)&xs[(1 * 6 + ul) * 32 + 2 * p];
            float2 xn = *(const float2*)&xs[(2 * 6 + ul) * 32 + 2 * p];
            float2 hold = *(const float2*)&Hs[j * 32 + 2 * p];

            float r0 = 1.f / (1.f + expf(-(xr.x + fR.x)));
            float r1 = 1.f / (1.f + expf(-(xr.y + fR.y)));
            float z0 = 1.f / (1.f + expf(-(xz.x + fZ.x)));
            float z1 = 1.f / (1.f + expf(-(xz.y + fZ.y)));
            float n0 = tanhf(xn.x + r0 * fN.x);
            float n1 = tanhf(xn.y + r1 * fN.y);
            float h0 = n0 + z0 * (hold.x - n0);
            float h1 = n1 + z1 * (hold.y - n1);

            __stcg((float2*)&g_H[dir][pp ^ 1][j * 32 + 2 * p], make_float2(h0, h1));
            Hn[slot]     = h0;
            Hn[slot + 1] = h1;
        }
        __syncthreads();

        if (tid == 0) red_release_add(&g_bar[dir * SS + s]);

        // OUT writes — off the critical path
        if (tid < 192) {
            int b2 = tid / 6, jj = tid - b2 * 6;
            g_OUT[(size_t)(t * 32 + b2) * (2 * HH) + dir * HH + u0 + jj] = Hn[jj * 32 + b2];
        }

        if (tid == 0) {
            while (ld_acquire(&g_bar[dir * SS + s]) < 64) { }
        }
        __syncthreads();
        pp ^= 1;
    }
}

// ------------------------- softmax + attention pooling ----------------------
__global__ void __launch_bounds__(256) attn_pool(float* __restrict__ out)
{
    __shared__ float sc[SS];
    __shared__ float red[256];
    const int b = blockIdx.x;
    const int tid = threadIdx.x;

    for (int t = tid; t < SS; t += 256) sc[t] = g_scores[t * 32 + b];
    __syncthreads();

    float mx = -3.4e38f;
    for (int t = tid; t < SS; t += 256) mx = fmaxf(mx, sc[t]);
    red[tid] = mx;
    __syncthreads();
    for (int sft = 128; sft > 0; sft >>= 1) {
        if (tid < sft) red[tid] = fmaxf(red[tid], red[tid + sft]);
        __syncthreads();
    }
    mx = red[0];
    __syncthreads();

    float lsum = 0.f;
    for (int t = tid; t < SS; t += 256) {
        float e = expf(sc[t] - mx);
        sc[t] = e;
        lsum += e;
    }
    red[tid] = lsum;
    __syncthreads();
    for (int sft = 128; sft > 0; sft >>= 1) {
        if (tid < sft) red[tid] += red[tid + sft];
        __syncthreads();
    }
    float inv = 1.f / red[0];
    __syncthreads();

#pragma unroll
    for (int pass = 0; pass < 3; ++pass) {
        int dd = pass * 256 + tid;
        float acc = 0.f;
#pragma unroll 4
        for (int t = 0; t < SS; ++t)
            acc = fmaf(sc[t], g_OUT[(size_t)(t * 32 + b) * (2 * HH) + dd], acc);
        out[b * (2 * HH) + dd] = acc * inv;
    }
}

// --------------------------------- launch -----------------------------------
extern "C" void kernel_launch(void* const* d_in, const int* in_sizes, int n_in,
                              void* d_out, int out_size)
{
    const float* ip   = (const float*)d_in[0];
    const float* Wihf = (const float*)d_in[1];
    const float* Whhf = (const float*)d_in[2];
    const float* bihf = (const float*)d_in[3];
    const float* bhhf = (const float*)d_in[4];
    const float* Wihb = (const float*)d_in[5];
    const float* Whhb = (const float*)d_in[6];
    const float* bihb = (const float*)d_in[7];
    const float* bhhb = (const float*)d_in[8];
    const float* Wa   = (const float*)d_in[9];
    const float* ba   = (const float*)d_in[10];
    const float* ctx  = (const float*)d_in[11];
    float* out = (float*)d_out;

    const __half *pAc, *pBc, *pWac, *pOc;
    cudaGetSymbolAddress((void**)&pAc, g_Ac);
    cudaGetSymbolAddress((void**)&pBc, g_Bc);
    cudaGetSymbolAddress((void**)&pWac, g_Wac);
    cudaGetSymbolAddress((void**)&pOc, g_Oc);

    const int rec_smem = REC_SMEM_FLOATS * 4;   // 114,664 bytes
    cudaFuncSetAttribute(gru_rec, cudaFuncAttributeMaxDynamicSharedMemorySize, rec_smem);
    cudaFuncSetAttribute(hgemm_kernel<0>, cudaFuncAttributeMaxDynamicSharedMemorySize, HG_DYN_SMEM);
    cudaFuncSetAttribute(hgemm_kernel<1>, cudaFuncAttributeMaxDynamicSharedMemorySize, HG_DYN_SMEM);

    init_kernel<<<64, 256>>>();
    {
        int tot = (M16K + NROWS + 2 * HH) * (DD / 4);
        convert_split<<<(tot + 255) / 256, 256>>>(ip, Wihf, Wihb, Wa);
    }
    hgemm_kernel<0><<<dim3(NROWS / 128, M16K / 128), 256, HG_DYN_SMEM>>>(
        pAc, pBc, bihf, bihb);
    gru_rec<<<128, REC_THREADS, rec_smem>>>(Whhf, Whhb, bhhf, bhhb);
    {
        int tot = M16K * (DD / 4);
        out_convert<<<(tot + 255) / 256, 256>>>();
    }
    hgemm_kernel<1><<<dim3((2 * HH) / 128, M16K / 128), 256, HG_DYN_SMEM>>>(
        pWac, pOc, ba, ctx);
    attn_pool<<<32, 256>>>(out);
}